// round 1
// baseline (speedup 1.0000x reference)
#include <cuda_runtime.h>
#include <math.h>

#define BB   2
#define LL   4096
#define HH   2048
#define DKK  128
#define CCH  64          // chunk length C
#define NCC  64          // chunks per batch
#define NTOK (BB*LL)     // 8192 tokens

// ---------------- scratch (static device globals; no allocation) ----------------
__device__ __align__(16) float g_qe[BB*LL*DKK];                 // q * exp(B)
__device__ __align__(16) float g_kd[BB*LL*DKK];                 // k * exp(Blast - B)
__device__ __align__(16) float g_eL[BB*NCC*DKK];                // exp(Blast)
__device__ __align__(16) float g_A [BB*NCC*CCH*CCH];            // intra-chunk A (tril)
__device__ __align__(16) float g_o [(size_t)NTOK*HH];           // GLA output, later h
__device__ __align__(16) float g_go[(size_t)NTOK*HH];           // gate pre-activation

// =================================================================================
// Kernel 1: per-chunk q/k projection + softmax/sigmoid + gf cumsum + qe/kd/eL + A
// grid = 128 blocks (b*NC), 256 threads, dynamic smem
// =================================================================================
#define SMEM1_FLOATS (3*64*128 + 128)
#define SMEM1_BYTES  (SMEM1_FLOATS*4)

__global__ void __launch_bounds__(256) qk_chunk_kernel(
    const float* __restrict__ x,
    const float* __restrict__ Wq,
    const float* __restrict__ Wk)
{
    extern __shared__ float sm[];
    // phase-B layout
    float* qs    = sm;              // 64*128
    float* ks    = sm + 64*128;     // 64*128
    float* bs    = sm + 2*64*128;   // 64*128 (cumsum B)
    float* blast = sm + 3*64*128;   // 128
    // phase-A layout (overlaps qs/ks; safe: regs carry accs across the sync)
    float* xs  = sm;                    // 32 x 64   (kk-major)
    float* wqs = sm + 32*64;            // 32 x 128
    float* wks = sm + 32*64 + 32*128;   // 32 x 128

    const int blk = blockIdx.x;
    const int b = blk / NCC, c = blk % NCC;
    const int tid = threadIdx.x;
    const float* xbase = x + ((size_t)(b*LL + c*CCH)) * HH;

    const int ty = tid >> 5;   // 0..7  -> token group
    const int tx = tid & 31;   // 0..31 -> column group

    float accq[8][4];
    float acck[8][4];
#pragma unroll
    for (int r = 0; r < 8; r++)
#pragma unroll
        for (int cc = 0; cc < 4; cc++) { accq[r][cc] = 0.f; acck[r][cc] = 0.f; }

    // ---- GEMM: y_q/y_k = x_chunk @ Wq^T / Wk^T  (64 x 128, K = 2048) ----
    for (int k0 = 0; k0 < HH; k0 += 32) {
        __syncthreads();
        {   // load x tile transposed: xs[kk][t]
            int t  = tid >> 2;
            int kk = (tid & 3) * 4;
            float4 v0 = *(const float4*)(xbase + (size_t)t*HH + k0 + kk);
            float4 v1 = *(const float4*)(xbase + (size_t)t*HH + k0 + kk + 16);
            xs[(kk+0)*64 + t] = v0.x; xs[(kk+1)*64 + t] = v0.y;
            xs[(kk+2)*64 + t] = v0.z; xs[(kk+3)*64 + t] = v0.w;
            xs[(kk+16)*64 + t] = v1.x; xs[(kk+17)*64 + t] = v1.y;
            xs[(kk+18)*64 + t] = v1.z; xs[(kk+19)*64 + t] = v1.w;
        }
        {   // load Wq / Wk tiles transposed: wqs[kk][r], wks[kk][r]
            int r  = tid >> 1;
            int kb = (tid & 1) * 4;
#pragma unroll
            for (int s = 0; s < 4; s++) {
                int kk = kb + s*8;
                float4 vq = *(const float4*)(Wq + (size_t)r*HH + k0 + kk);
                wqs[(kk+0)*128 + r] = vq.x; wqs[(kk+1)*128 + r] = vq.y;
                wqs[(kk+2)*128 + r] = vq.z; wqs[(kk+3)*128 + r] = vq.w;
                float4 vk = *(const float4*)(Wk + (size_t)r*HH + k0 + kk);
                wks[(kk+0)*128 + r] = vk.x; wks[(kk+1)*128 + r] = vk.y;
                wks[(kk+2)*128 + r] = vk.z; wks[(kk+3)*128 + r] = vk.w;
            }
        }
        __syncthreads();
#pragma unroll
        for (int kk = 0; kk < 32; kk++) {
            float xv[8];
#pragma unroll
            for (int r = 0; r < 8; r++) xv[r] = xs[kk*64 + ty + 8*r];
            float wqv[4], wkv[4];
#pragma unroll
            for (int cc = 0; cc < 4; cc++) {
                wqv[cc] = wqs[kk*128 + tx + 32*cc];
                wkv[cc] = wks[kk*128 + tx + 32*cc];
            }
#pragma unroll
            for (int r = 0; r < 8; r++)
#pragma unroll
                for (int cc = 0; cc < 4; cc++) {
                    accq[r][cc] += xv[r]*wqv[cc];
                    acck[r][cc] += xv[r]*wkv[cc];
                }
        }
    }
    __syncthreads();

    // ---- write logits: qs = raw q-logits, ks = sigmoid(k-logits) ----
#pragma unroll
    for (int r = 0; r < 8; r++)
#pragma unroll
        for (int cc = 0; cc < 4; cc++) {
            int t = ty + 8*r, d = tx + 32*cc;
            qs[t*128 + d] = accq[r][cc];
            ks[t*128 + d] = 1.f / (1.f + __expf(-acck[r][cc]));
        }
    __syncthreads();

    // ---- softmax q rows (token per thread) ----
    if (tid < 64) {
        float m = -1e30f;
        for (int d = 0; d < 128; d++) m = fmaxf(m, qs[tid*128 + d]);
        float s = 0.f;
        for (int d = 0; d < 128; d++) {
            float e = __expf(qs[tid*128 + d] - m);
            qs[tid*128 + d] = e; s += e;
        }
        float inv = 1.f / s;
        for (int d = 0; d < 128; d++) qs[tid*128 + d] *= inv;
    }
    // ---- gf = -log(1+exp(k)); inclusive cumsum per channel ----
    if (tid < 128) {
        int d = tid;
        float acc = 0.f;
        for (int t = 0; t < 64; t++) {
            float kv = ks[t*128 + d];
            acc += -log1pf(__expf(kv));
            bs[t*128 + d] = acc;
        }
        blast[d] = acc;
        g_eL[blk*128 + d] = __expf(acc);
    }
    __syncthreads();

    // ---- qe / kd to global ----
    {
        size_t base = ((size_t)(b*LL + c*CCH)) * DKK;
        for (int idx = tid; idx < 64*128; idx += 256) {
            int d = idx & 127;
            float bv = bs[idx];
            g_qe[base + idx] = qs[idx] * __expf(bv);
            g_kd[base + idx] = ks[idx] * __expf(blast[d] - bv);
        }
    }
    // ---- A[i][j] = sum_d q[i,d] k[j,d] exp(B[i,d]-B[j,d]), i>=j ----
    {
        float* Ag = g_A + (size_t)blk * CCH * CCH;
        for (int p = tid; p < 64*64; p += 256) {
            int i = p >> 6, j = p & 63;
            float a = 0.f;
            if (i >= j) {
                const float* qi = qs + i*128;
                const float* kj = ks + j*128;
                const float* bi = bs + i*128;
                const float* bj = bs + j*128;
#pragma unroll 4
                for (int d = 0; d < 128; d++)
                    a += qi[d] * kj[d] * __expf(bi[d] - bj[d]);
            }
            Ag[p] = a;
        }
    }
}

// =================================================================================
// Kernel 2: chunked GLA recurrence. grid (H/32, B) = (64, 2), 256 threads.
// State tile S[128][32] lives in SMEM; chunks processed sequentially.
// =================================================================================
#define SMEM2_FLOATS (8192 + 8192 + 4096 + 2048 + 4096 + 128)
#define SMEM2_BYTES  (SMEM2_FLOATS*4)

__global__ void __launch_bounds__(256) recurrence_kernel(const float* __restrict__ x)
{
    extern __shared__ float sm[];
    float* qe_s = sm;              // 64*128
    float* kd_s = sm + 8192;       // 64*128
    float* A_s  = sm + 16384;      // 64*64
    float* v_s  = sm + 20480;      // 64*32
    float* S_s  = sm + 22528;      // 128*32
    float* eL_s = sm + 26624;      // 128

    const int b  = blockIdx.y;
    const int v0 = blockIdx.x * 32;
    const int tid = threadIdx.x;
    const int tx = tid & 15;       // v-pair
    const int ty = tid >> 4;       // 0..15
    const int vv = 2*tx;

    for (int i = tid; i < 128*32; i += 256) S_s[i] = 0.f;

    for (int c = 0; c < NCC; c++) {
        __syncthreads();
        // ---- loads ----
        {
            size_t base = ((size_t)(b*LL + c*CCH)) * DKK;
            for (int idx = tid*4; idx < 8192; idx += 1024) {
                *(float4*)(qe_s + idx) = *(const float4*)(g_qe + base + idx);
                *(float4*)(kd_s + idx) = *(const float4*)(g_kd + base + idx);
            }
            const float* Ag = g_A + (size_t)(b*NCC + c) * 4096;
            for (int idx = tid*4; idx < 4096; idx += 1024)
                *(float4*)(A_s + idx) = *(const float4*)(Ag + idx);
            for (int idx = tid; idx < 64*32; idx += 256) {
                int t = idx >> 5, j = idx & 31;
                v_s[idx] = x[((size_t)(b*LL + c*CCH + t)) * HH + v0 + j];
            }
            if (tid < 128) eL_s[tid] = g_eL[(b*NCC + c)*128 + tid];
        }
        __syncthreads();

        // ---- o = A@v + (q e^B)@S  (rows i = ty + 16r, cols vv, vv+1) ----
        float o0[4] = {0,0,0,0}, o1[4] = {0,0,0,0};
        for (int j = 0; j < 64; j++) {
            float2 vj = *(float2*)(v_s + j*32 + vv);
#pragma unroll
            for (int r = 0; r < 4; r++) {
                float a = A_s[(ty + 16*r)*64 + j];
                o0[r] += a * vj.x; o1[r] += a * vj.y;
            }
        }
        for (int d = 0; d < 128; d++) {
            float2 sv = *(float2*)(S_s + d*32 + vv);
#pragma unroll
            for (int r = 0; r < 4; r++) {
                float qv = qe_s[(ty + 16*r)*128 + d];
                o0[r] += qv * sv.x; o1[r] += qv * sv.y;
            }
        }
#pragma unroll
        for (int r = 0; r < 4; r++) {
            size_t row = (size_t)(b*LL + c*CCH + ty + 16*r);
            *(float2*)(g_o + row*HH + v0 + vv) = make_float2(o0[r], o1[r]);
        }

        // ---- S-update accumulators: d = ty*8 + dd ----
        float a0[8] = {0,0,0,0,0,0,0,0}, a1[8] = {0,0,0,0,0,0,0,0};
        for (int j = 0; j < 64; j++) {
            float2 vj = *(float2*)(v_s + j*32 + vv);
            float4 k0 = *(float4*)(kd_s + j*128 + ty*8);
            float4 k1 = *(float4*)(kd_s + j*128 + ty*8 + 4);
            a0[0] += k0.x*vj.x; a1[0] += k0.x*vj.y;
            a0[1] += k0.y*vj.x; a1[1] += k0.y*vj.y;
            a0[2] += k0.z*vj.x; a1[2] += k0.z*vj.y;
            a0[3] += k0.w*vj.x; a1[3] += k0.w*vj.y;
            a0[4] += k1.x*vj.x; a1[4] += k1.x*vj.y;
            a0[5] += k1.y*vj.x; a1[5] += k1.y*vj.y;
            a0[6] += k1.z*vj.x; a1[6] += k1.z*vj.y;
            a0[7] += k1.w*vj.x; a1[7] += k1.w*vj.y;
        }
        __syncthreads();   // everyone done reading old S
#pragma unroll
        for (int dd = 0; dd < 8; dd++) {
            int d = ty*8 + dd;
            float e = eL_s[d];
            S_s[d*32 + vv]     = S_s[d*32 + vv]     * e + a0[dd];
            S_s[d*32 + vv + 1] = S_s[d*32 + vv + 1] * e + a1[dd];
        }
        // loop-top __syncthreads() orders S writes & eL reuse vs next loads
    }
}

// =================================================================================
// Kernel 3: SGEMM  C[M,N] (+)= A[M,K] @ B[N,K]^T   (128x128x16 tiles, 8x8 micro)
// =================================================================================
template<int DO_ADD>
__global__ void __launch_bounds__(256) sgemm_nt_kernel(
    const float* __restrict__ A, const float* __restrict__ Bw,
    float* __restrict__ Cmat, int M, int N, int K)
{
    __shared__ float As[2][16][128];
    __shared__ float Bs[2][16][128];
    const int tid = threadIdx.x;
    const int m0 = blockIdx.y * 128;
    const int n0 = blockIdx.x * 128;
    const int row = tid >> 2;
    const int kk4 = (tid & 3) << 2;
    const float* ap = A  + (size_t)(m0 + row) * K + kk4;
    const float* bp = Bw + (size_t)(n0 + row) * K + kk4;
    const int tm = (tid >> 4) << 3;
    const int tn = (tid & 15) << 3;

    float4 ra0, ra1, rb0, rb1;
    ra0 = *(const float4*)(ap);
    ra1 = *(const float4*)(ap + (size_t)64 * K);
    rb0 = *(const float4*)(bp);
    rb1 = *(const float4*)(bp + (size_t)64 * K);
#pragma unroll
    for (int j = 0; j < 4; j++) {
        As[0][kk4 + j][row]      = ((float*)&ra0)[j];
        As[0][kk4 + j][row + 64] = ((float*)&ra1)[j];
        Bs[0][kk4 + j][row]      = ((float*)&rb0)[j];
        Bs[0][kk4 + j][row + 64] = ((float*)&rb1)[j];
    }
    __syncthreads();

    float acc[8][8];
#pragma unroll
    for (int i = 0; i < 8; i++)
#pragma unroll
        for (int j = 0; j < 8; j++) acc[i][j] = 0.f;

    const int nk = K >> 4;
    for (int kt = 0; kt < nk; kt++) {
        int cur = kt & 1;
        if (kt + 1 < nk) {
            const float* ap2 = ap + (kt + 1) * 16;
            const float* bp2 = bp + (kt + 1) * 16;
            ra0 = *(const float4*)(ap2);
            ra1 = *(const float4*)(ap2 + (size_t)64 * K);
            rb0 = *(const float4*)(bp2);
            rb1 = *(const float4*)(bp2 + (size_t)64 * K);
        }
#pragma unroll
        for (int kk = 0; kk < 16; kk++) {
            float a[8], bv[8];
            *(float4*)&a[0]  = *(const float4*)&As[cur][kk][tm];
            *(float4*)&a[4]  = *(const float4*)&As[cur][kk][tm + 4];
            *(float4*)&bv[0] = *(const float4*)&Bs[cur][kk][tn];
            *(float4*)&bv[4] = *(const float4*)&Bs[cur][kk][tn + 4];
#pragma unroll
            for (int i = 0; i < 8; i++)
#pragma unroll
                for (int j = 0; j < 8; j++)
                    acc[i][j] += a[i] * bv[j];
        }
        if (kt + 1 < nk) {
            int nxt = cur ^ 1;
#pragma unroll
            for (int j = 0; j < 4; j++) {
                As[nxt][kk4 + j][row]      = ((float*)&ra0)[j];
                As[nxt][kk4 + j][row + 64] = ((float*)&ra1)[j];
                Bs[nxt][kk4 + j][row]      = ((float*)&rb0)[j];
                Bs[nxt][kk4 + j][row + 64] = ((float*)&rb1)[j];
            }
        }
        __syncthreads();
    }

#pragma unroll
    for (int i = 0; i < 8; i++) {
        float* cp = Cmat + (size_t)(m0 + tm + i) * N + n0 + tn;
        if (DO_ADD) {
            float4 c0 = *(float4*)cp;
            float4 c1 = *(float4*)(cp + 4);
            c0.x += acc[i][0]; c0.y += acc[i][1]; c0.z += acc[i][2]; c0.w += acc[i][3];
            c1.x += acc[i][4]; c1.y += acc[i][5]; c1.z += acc[i][6]; c1.w += acc[i][7];
            *(float4*)cp = c0; *(float4*)(cp + 4) = c1;
        } else {
            *(float4*)cp       = make_float4(acc[i][0], acc[i][1], acc[i][2], acc[i][3]);
            *(float4*)(cp + 4) = make_float4(acc[i][4], acc[i][5], acc[i][6], acc[i][7]);
        }
    }
}

// =================================================================================
// Kernel 4: h = rmsnorm(o)*g * silu(go)   (in-place into g_o)
// =================================================================================
__global__ void __launch_bounds__(256) rms_silu_kernel(const float* __restrict__ gnw)
{
    __shared__ float red[256];
    const size_t row = blockIdx.x;
    float* orow  = g_o  + row * HH;
    const float* gorow = g_go + row * HH;
    const int tid = threadIdx.x;

    float s = 0.f;
    for (int i = tid; i < HH; i += 256) { float v = orow[i]; s += v*v; }
    red[tid] = s;
    __syncthreads();
    for (int off = 128; off > 0; off >>= 1) {
        if (tid < off) red[tid] += red[tid + off];
        __syncthreads();
    }
    float rinv = rsqrtf(red[0] * (1.f / (float)HH) + 1e-5f);

    for (int i = tid; i < HH; i += 256) {
        float ov = orow[i] * rinv * gnw[i];
        float g  = gorow[i];
        float sig = 1.f / (1.f + __expf(-g));
        orow[i] = ov * (g * sig);
    }
}

// =================================================================================
extern "C" void kernel_launch(void* const* d_in, const int* in_sizes, int n_in,
                              void* d_out, int out_size)
{
    const float* x   = (const float*)d_in[0];
    const float* Wq  = (const float*)d_in[1];
    const float* Wk  = (const float*)d_in[2];
    const float* Wog = (const float*)d_in[3];
    const float* Wig = (const float*)d_in[4];
    const float* Wo  = (const float*)d_in[5];
    const float* gnw = (const float*)d_in[6];
    float* out = (float*)d_out;

    cudaFuncSetAttribute(qk_chunk_kernel,
                         cudaFuncAttributeMaxDynamicSharedMemorySize, SMEM1_BYTES);
    cudaFuncSetAttribute(recurrence_kernel,
                         cudaFuncAttributeMaxDynamicSharedMemorySize, SMEM2_BYTES);

    float *p_o, *p_go;
    cudaGetSymbolAddress((void**)&p_o,  g_o);
    cudaGetSymbolAddress((void**)&p_go, g_go);

    // 1) projections + gating precompute + intra-chunk A
    qk_chunk_kernel<<<BB*NCC, 256, SMEM1_BYTES>>>(x, Wq, Wk);
    // 2) chunked recurrence -> g_o
    recurrence_kernel<<<dim3(HH/32, BB), 256, SMEM2_BYTES>>>(x);
    // 3) go = x @ Wig^T + o @ Wog^T
    sgemm_nt_kernel<0><<<dim3(HH/128, NTOK/128), 256>>>(x,   Wig, p_go, NTOK, HH, HH);
    sgemm_nt_kernel<1><<<dim3(HH/128, NTOK/128), 256>>>(p_o, Wog, p_go, NTOK, HH, HH);
    // 4) h = rmsnorm(o)*g * silu(go)  (in place, g_o -> h)
    rms_silu_kernel<<<NTOK, 256>>>(gnw);
    // 5) out = h @ Wo^T
    sgemm_nt_kernel<0><<<dim3(HH/128, NTOK/128), 256>>>(p_o, Wo, out, NTOK, HH, HH);
}

// round 3
// speedup vs baseline: 1.7868x; 1.7868x over previous
#include <cuda_runtime.h>
#include <math.h>
#include <stdint.h>

#define BB   2
#define LL   4096
#define HH   2048
#define DKK  128
#define CCH  64          // chunk length C
#define NCC  64          // chunks per batch
#define NTOK (BB*LL)     // 8192 tokens

// ---------------- scratch (static device globals; no allocation) ----------------
__device__ __align__(16) float g_qe[BB*LL*DKK];                 // q * exp(B)
__device__ __align__(16) float g_kd[BB*LL*DKK];                 // k * exp(Blast - B)
__device__ __align__(16) float g_eL[BB*NCC*DKK];                // exp(Blast)
__device__ __align__(16) float g_A [BB*NCC*CCH*CCH];            // intra-chunk A (tril)
__device__ __align__(16) float g_o [(size_t)NTOK*HH];           // GLA output (tf32-rounded), later h
__device__ __align__(16) float g_go[(size_t)NTOK*HH];           // gate pre-activation
__device__ __align__(16) float g_xt [(size_t)NTOK*HH];          // tf32-rounded x
__device__ __align__(16) float g_wig[(size_t)HH*HH];            // tf32-rounded Wig
__device__ __align__(16) float g_wog[(size_t)HH*HH];            // tf32-rounded Wog
__device__ __align__(16) float g_wo [(size_t)HH*HH];            // tf32-rounded Wo

// ================================ helpers ========================================
__device__ __forceinline__ float tf32r(float x) {
    uint32_t o;
    asm("cvt.rna.tf32.f32 %0, %1;" : "=r"(o) : "f"(x));
    return __uint_as_float(o);
}

// D += A*B : m16n8k8 tf32 (sm_80+ PTX, runs on plain sm_103)
__device__ __forceinline__ void mma16n8k8(float d[4],
                                          uint32_t a0, uint32_t a1, uint32_t a2, uint32_t a3,
                                          uint32_t b0, uint32_t b1) {
    asm("mma.sync.aligned.m16n8k8.row.col.f32.tf32.tf32.f32 "
        "{%0,%1,%2,%3}, {%4,%5,%6,%7}, {%8,%9}, {%0,%1,%2,%3};"
        : "+f"(d[0]), "+f"(d[1]), "+f"(d[2]), "+f"(d[3])
        : "r"(a0), "r"(a1), "r"(a2), "r"(a3), "r"(b0), "r"(b1));
}

// =================================================================================
// Kernel 0: RN round to tf32
// =================================================================================
__global__ void __launch_bounds__(256) conv_tf32_kernel(
    const float* __restrict__ src, float* __restrict__ dst, int n4)
{
    int i = blockIdx.x*256 + threadIdx.x;
    if (i < n4) {
        float4 v = ((const float4*)src)[i];
        v.x = tf32r(v.x); v.y = tf32r(v.y); v.z = tf32r(v.z); v.w = tf32r(v.w);
        ((float4*)dst)[i] = v;
    }
}

// =================================================================================
// Kernel 1: per-chunk q/k projection + softmax/sigmoid + gf cumsum + qe/kd/eL + A
// =================================================================================
#define SMEM1_FLOATS (3*64*128 + 128)
#define SMEM1_BYTES  (SMEM1_FLOATS*4)

__global__ void __launch_bounds__(256) qk_chunk_kernel(
    const float* __restrict__ x,
    const float* __restrict__ Wq,
    const float* __restrict__ Wk)
{
    extern __shared__ float sm[];
    float* qs    = sm;              // 64*128
    float* ks    = sm + 64*128;     // 64*128
    float* bs    = sm + 2*64*128;   // 64*128 (cumsum B)
    float* blast = sm + 3*64*128;   // 128
    float* xs  = sm;                    // 32 x 64   (kk-major)
    float* wqs = sm + 32*64;            // 32 x 128
    float* wks = sm + 32*64 + 32*128;   // 32 x 128

    const int blk = blockIdx.x;
    const int b = blk / NCC, c = blk % NCC;
    const int tid = threadIdx.x;
    const float* xbase = x + ((size_t)(b*LL + c*CCH)) * HH;

    const int ty = tid >> 5;
    const int tx = tid & 31;

    float accq[8][4];
    float acck[8][4];
#pragma unroll
    for (int r = 0; r < 8; r++)
#pragma unroll
        for (int cc = 0; cc < 4; cc++) { accq[r][cc] = 0.f; acck[r][cc] = 0.f; }

    for (int k0 = 0; k0 < HH; k0 += 32) {
        __syncthreads();
        {
            int t  = tid >> 2;
            int kk = (tid & 3) * 4;
            float4 v0 = *(const float4*)(xbase + (size_t)t*HH + k0 + kk);
            float4 v1 = *(const float4*)(xbase + (size_t)t*HH + k0 + kk + 16);
            xs[(kk+0)*64 + t] = v0.x; xs[(kk+1)*64 + t] = v0.y;
            xs[(kk+2)*64 + t] = v0.z; xs[(kk+3)*64 + t] = v0.w;
            xs[(kk+16)*64 + t] = v1.x; xs[(kk+17)*64 + t] = v1.y;
            xs[(kk+18)*64 + t] = v1.z; xs[(kk+19)*64 + t] = v1.w;
        }
        {
            int r  = tid >> 1;
            int kb = (tid & 1) * 4;
#pragma unroll
            for (int s = 0; s < 4; s++) {
                int kk = kb + s*8;
                float4 vq = *(const float4*)(Wq + (size_t)r*HH + k0 + kk);
                wqs[(kk+0)*128 + r] = vq.x; wqs[(kk+1)*128 + r] = vq.y;
                wqs[(kk+2)*128 + r] = vq.z; wqs[(kk+3)*128 + r] = vq.w;
                float4 vk = *(const float4*)(Wk + (size_t)r*HH + k0 + kk);
                wks[(kk+0)*128 + r] = vk.x; wks[(kk+1)*128 + r] = vk.y;
                wks[(kk+2)*128 + r] = vk.z; wks[(kk+3)*128 + r] = vk.w;
            }
        }
        __syncthreads();
#pragma unroll
        for (int kk = 0; kk < 32; kk++) {
            float xv[8];
#pragma unroll
            for (int r = 0; r < 8; r++) xv[r] = xs[kk*64 + ty + 8*r];
            float wqv[4], wkv[4];
#pragma unroll
            for (int cc = 0; cc < 4; cc++) {
                wqv[cc] = wqs[kk*128 + tx + 32*cc];
                wkv[cc] = wks[kk*128 + tx + 32*cc];
            }
#pragma unroll
            for (int r = 0; r < 8; r++)
#pragma unroll
                for (int cc = 0; cc < 4; cc++) {
                    accq[r][cc] += xv[r]*wqv[cc];
                    acck[r][cc] += xv[r]*wkv[cc];
                }
        }
    }
    __syncthreads();

#pragma unroll
    for (int r = 0; r < 8; r++)
#pragma unroll
        for (int cc = 0; cc < 4; cc++) {
            int t = ty + 8*r, d = tx + 32*cc;
            qs[t*128 + d] = accq[r][cc];
            ks[t*128 + d] = 1.f / (1.f + __expf(-acck[r][cc]));
        }
    __syncthreads();

    if (tid < 64) {
        float m = -1e30f;
        for (int d = 0; d < 128; d++) m = fmaxf(m, qs[tid*128 + d]);
        float s = 0.f;
        for (int d = 0; d < 128; d++) {
            float e = __expf(qs[tid*128 + d] - m);
            qs[tid*128 + d] = e; s += e;
        }
        float inv = 1.f / s;
        for (int d = 0; d < 128; d++) qs[tid*128 + d] *= inv;
    }
    if (tid < 128) {
        int d = tid;
        float acc = 0.f;
        for (int t = 0; t < 64; t++) {
            float kv = ks[t*128 + d];
            acc += -log1pf(__expf(kv));
            bs[t*128 + d] = acc;
        }
        blast[d] = acc;
        g_eL[blk*128 + d] = __expf(acc);
    }
    __syncthreads();

    {
        size_t base = ((size_t)(b*LL + c*CCH)) * DKK;
        for (int idx = tid; idx < 64*128; idx += 256) {
            int d = idx & 127;
            float bv = bs[idx];
            g_qe[base + idx] = qs[idx] * __expf(bv);
            g_kd[base + idx] = ks[idx] * __expf(blast[d] - bv);
        }
    }
    {
        float* Ag = g_A + (size_t)blk * CCH * CCH;
        for (int p = tid; p < 64*64; p += 256) {
            int i = p >> 6, j = p & 63;
            float a = 0.f;
            if (i >= j) {
                const float* qi = qs + i*128;
                const float* kj = ks + j*128;
                const float* bi = bs + i*128;
                const float* bj = bs + j*128;
#pragma unroll 4
                for (int d = 0; d < 128; d++)
                    a += qi[d] * kj[d] * __expf(bi[d] - bj[d]);
            }
            Ag[p] = a;
        }
    }
}

// =================================================================================
// Kernel 2: chunked GLA recurrence (o stores are tf32-rounded for the tf32 GEMM)
// =================================================================================
#define SMEM2_FLOATS (8192 + 8192 + 4096 + 2048 + 4096 + 128)
#define SMEM2_BYTES  (SMEM2_FLOATS*4)

__global__ void __launch_bounds__(256) recurrence_kernel(const float* __restrict__ x)
{
    extern __shared__ float sm[];
    float* qe_s = sm;              // 64*128
    float* kd_s = sm + 8192;       // 64*128
    float* A_s  = sm + 16384;      // 64*64
    float* v_s  = sm + 20480;      // 64*32
    float* S_s  = sm + 22528;      // 128*32
    float* eL_s = sm + 26624;      // 128

    const int b  = blockIdx.y;
    const int v0 = blockIdx.x * 32;
    const int tid = threadIdx.x;
    const int tx = tid & 15;
    const int ty = tid >> 4;
    const int vv = 2*tx;

    for (int i = tid; i < 128*32; i += 256) S_s[i] = 0.f;

    for (int c = 0; c < NCC; c++) {
        __syncthreads();
        {
            size_t base = ((size_t)(b*LL + c*CCH)) * DKK;
            for (int idx = tid*4; idx < 8192; idx += 1024) {
                *(float4*)(qe_s + idx) = *(const float4*)(g_qe + base + idx);
                *(float4*)(kd_s + idx) = *(const float4*)(g_kd + base + idx);
            }
            const float* Ag = g_A + (size_t)(b*NCC + c) * 4096;
            for (int idx = tid*4; idx < 4096; idx += 1024)
                *(float4*)(A_s + idx) = *(const float4*)(Ag + idx);
            for (int idx = tid; idx < 64*32; idx += 256) {
                int t = idx >> 5, j = idx & 31;
                v_s[idx] = x[((size_t)(b*LL + c*CCH + t)) * HH + v0 + j];
            }
            if (tid < 128) eL_s[tid] = g_eL[(b*NCC + c)*128 + tid];
        }
        __syncthreads();

        float o0[4] = {0,0,0,0}, o1[4] = {0,0,0,0};
        for (int j = 0; j < 64; j++) {
            float2 vj = *(float2*)(v_s + j*32 + vv);
#pragma unroll
            for (int r = 0; r < 4; r++) {
                float a = A_s[(ty + 16*r)*64 + j];
                o0[r] += a * vj.x; o1[r] += a * vj.y;
            }
        }
        for (int d = 0; d < 128; d++) {
            float2 sv = *(float2*)(S_s + d*32 + vv);
#pragma unroll
            for (int r = 0; r < 4; r++) {
                float qv = qe_s[(ty + 16*r)*128 + d];
                o0[r] += qv * sv.x; o1[r] += qv * sv.y;
            }
        }
#pragma unroll
        for (int r = 0; r < 4; r++) {
            size_t row = (size_t)(b*LL + c*CCH + ty + 16*r);
            *(float2*)(g_o + row*HH + v0 + vv) = make_float2(tf32r(o0[r]), tf32r(o1[r]));
        }

        float a0[8] = {0,0,0,0,0,0,0,0}, a1[8] = {0,0,0,0,0,0,0,0};
        for (int j = 0; j < 64; j++) {
            float2 vj = *(float2*)(v_s + j*32 + vv);
            float4 k0 = *(float4*)(kd_s + j*128 + ty*8);
            float4 k1 = *(float4*)(kd_s + j*128 + ty*8 + 4);
            a0[0] += k0.x*vj.x; a1[0] += k0.x*vj.y;
            a0[1] += k0.y*vj.x; a1[1] += k0.y*vj.y;
            a0[2] += k0.z*vj.x; a1[2] += k0.z*vj.y;
            a0[3] += k0.w*vj.x; a1[3] += k0.w*vj.y;
            a0[4] += k1.x*vj.x; a1[4] += k1.x*vj.y;
            a0[5] += k1.y*vj.x; a1[5] += k1.y*vj.y;
            a0[6] += k1.z*vj.x; a1[6] += k1.z*vj.y;
            a0[7] += k1.w*vj.x; a1[7] += k1.w*vj.y;
        }
        __syncthreads();
#pragma unroll
        for (int dd = 0; dd < 8; dd++) {
            int d = ty*8 + dd;
            float e = eL_s[d];
            S_s[d*32 + vv]     = S_s[d*32 + vv]     * e + a0[dd];
            S_s[d*32 + vv + 1] = S_s[d*32 + vv + 1] * e + a1[dd];
        }
    }
}

// =================================================================================
// Kernel 3: tf32 mma.sync GEMM.  C[8192,2048] = A@B^T (dual-source K possible).
// CTA tile 128x128, BK=16, 8 warps (2x4) each 64x32 warp tile of m16n8k8 MMAs.
// smem k-major [k][m], pad 132 floats. nk ktiles of 16; source switch at kt=128.
// =================================================================================
#define PADM 132

__global__ void __launch_bounds__(256) gemm_mma_kernel(
    const float* __restrict__ A1, const float* __restrict__ B1,
    const float* __restrict__ A2, const float* __restrict__ B2,
    float* __restrict__ Cmat, int nk)
{
    __shared__ float As[2][16*PADM];
    __shared__ float Bs[2][16*PADM];

    const int tid = threadIdx.x;
    const int m0 = blockIdx.y * 128;
    const int n0 = blockIdx.x * 128;
    const int row = tid >> 2;            // 0..63 (loader row)
    const int kk4 = (tid & 3) << 2;      // 0,4,8,12
    const int warp = tid >> 5, lane = tid & 31;
    const int wm = (warp & 1) * 64;      // warp m offset
    const int wn = (warp >> 1) * 32;     // warp n offset
    const int g = lane >> 2, t = lane & 3;

    float acc[4][4][4];
#pragma unroll
    for (int i = 0; i < 4; i++)
#pragma unroll
        for (int j = 0; j < 4; j++)
#pragma unroll
            for (int k = 0; k < 4; k++) acc[i][j][k] = 0.f;

    float4 ra0, ra1, rb0, rb1;

    // ---- load ktile 0 ----
    {
        const float* Ab = A1 + (size_t)(m0 + row) * HH + kk4;
        const float* Bb = B1 + (size_t)(n0 + row) * HH + kk4;
        ra0 = *(const float4*)(Ab);
        ra1 = *(const float4*)(Ab + (size_t)64 * HH);
        rb0 = *(const float4*)(Bb);
        rb1 = *(const float4*)(Bb + (size_t)64 * HH);
    }
#pragma unroll
    for (int j = 0; j < 4; j++) {
        As[0][(kk4+j)*PADM + row]      = ((float*)&ra0)[j];
        As[0][(kk4+j)*PADM + row + 64] = ((float*)&ra1)[j];
        Bs[0][(kk4+j)*PADM + row]      = ((float*)&rb0)[j];
        Bs[0][(kk4+j)*PADM + row + 64] = ((float*)&rb1)[j];
    }
    __syncthreads();

    for (int kt = 0; kt < nk; kt++) {
        const int cur = kt & 1;
        if (kt + 1 < nk) {
            int nx = kt + 1;
            const float* Ab; const float* Bb;
            if (nx < 128) { Ab = A1; Bb = B1; } else { Ab = A2; Bb = B2; }
            int kof = (nx & 127) * 16 + kk4;
            Ab += (size_t)(m0 + row) * HH + kof;
            Bb += (size_t)(n0 + row) * HH + kof;
            ra0 = *(const float4*)(Ab);
            ra1 = *(const float4*)(Ab + (size_t)64 * HH);
            rb0 = *(const float4*)(Bb);
            rb1 = *(const float4*)(Bb + (size_t)64 * HH);
        }

#pragma unroll
        for (int ks = 0; ks < 2; ks++) {
            const float* pAlo = &As[cur][(ks*8 + t)*PADM];
            const float* pAhi = &As[cur][(ks*8 + t + 4)*PADM];
            const float* pBlo = &Bs[cur][(ks*8 + t)*PADM];
            const float* pBhi = &Bs[cur][(ks*8 + t + 4)*PADM];

            uint32_t a[4][4];
#pragma unroll
            for (int mt = 0; mt < 4; mt++) {
                int r = wm + mt*16 + g;
                a[mt][0] = __float_as_uint(pAlo[r]);
                a[mt][1] = __float_as_uint(pAlo[r + 8]);
                a[mt][2] = __float_as_uint(pAhi[r]);
                a[mt][3] = __float_as_uint(pAhi[r + 8]);
            }
            uint32_t b[4][2];
#pragma unroll
            for (int nt = 0; nt < 4; nt++) {
                int cidx = wn + nt*8 + g;
                b[nt][0] = __float_as_uint(pBlo[cidx]);
                b[nt][1] = __float_as_uint(pBhi[cidx]);
            }
#pragma unroll
            for (int mt = 0; mt < 4; mt++)
#pragma unroll
                for (int nt = 0; nt < 4; nt++)
                    mma16n8k8(acc[mt][nt],
                              a[mt][0], a[mt][1], a[mt][2], a[mt][3],
                              b[nt][0], b[nt][1]);
        }

        if (kt + 1 < nk) {
            const int nxt = cur ^ 1;
#pragma unroll
            for (int j = 0; j < 4; j++) {
                As[nxt][(kk4+j)*PADM + row]      = ((float*)&ra0)[j];
                As[nxt][(kk4+j)*PADM + row + 64] = ((float*)&ra1)[j];
                Bs[nxt][(kk4+j)*PADM + row]      = ((float*)&rb0)[j];
                Bs[nxt][(kk4+j)*PADM + row + 64] = ((float*)&rb1)[j];
            }
        }
        __syncthreads();
    }

    // ---- epilogue ----
#pragma unroll
    for (int mt = 0; mt < 4; mt++) {
        int r0 = m0 + wm + mt*16 + g;
#pragma unroll
        for (int nt = 0; nt < 4; nt++) {
            int c = n0 + wn + nt*8 + 2*t;
            *(float2*)(Cmat + (size_t)r0*HH + c) =
                make_float2(acc[mt][nt][0], acc[mt][nt][1]);
            *(float2*)(Cmat + (size_t)(r0+8)*HH + c) =
                make_float2(acc[mt][nt][2], acc[mt][nt][3]);
        }
    }
}

// =================================================================================
// Kernel 4: h = rmsnorm(o)*g * silu(go)  (in-place into g_o, tf32-rounded)
// =================================================================================
__global__ void __launch_bounds__(256) rms_silu_kernel(const float* __restrict__ gnw)
{
    __shared__ float red[256];
    const size_t row = blockIdx.x;
    float* orow  = g_o  + row * HH;
    const float* gorow = g_go + row * HH;
    const int tid = threadIdx.x;

    float s = 0.f;
    for (int i = tid; i < HH; i += 256) { float v = orow[i]; s += v*v; }
    red[tid] = s;
    __syncthreads();
    for (int off = 128; off > 0; off >>= 1) {
        if (tid < off) red[tid] += red[tid + off];
        __syncthreads();
    }
    float rinv = rsqrtf(red[0] * (1.f / (float)HH) + 1e-5f);

    for (int i = tid; i < HH; i += 256) {
        float ov = orow[i] * rinv * gnw[i];
        float g  = gorow[i];
        float sig = 1.f / (1.f + __expf(-g));
        orow[i] = tf32r(ov * (g * sig));
    }
}

// ================================= host side =====================================
extern "C" void kernel_launch(void* const* d_in, const int* in_sizes, int n_in,
                              void* d_out, int out_size)
{
    const float* x   = (const float*)d_in[0];
    const float* Wq  = (const float*)d_in[1];
    const float* Wk  = (const float*)d_in[2];
    const float* Wog = (const float*)d_in[3];
    const float* Wig = (const float*)d_in[4];
    const float* Wo  = (const float*)d_in[5];
    const float* gnw = (const float*)d_in[6];
    float* out = (float*)d_out;

    cudaFuncSetAttribute(qk_chunk_kernel,
                         cudaFuncAttributeMaxDynamicSharedMemorySize, SMEM1_BYTES);
    cudaFuncSetAttribute(recurrence_kernel,
                         cudaFuncAttributeMaxDynamicSharedMemorySize, SMEM2_BYTES);

    float *p_o, *p_go, *p_xt, *p_wig, *p_wog, *p_wo;
    cudaGetSymbolAddress((void**)&p_o,   g_o);
    cudaGetSymbolAddress((void**)&p_go,  g_go);
    cudaGetSymbolAddress((void**)&p_xt,  g_xt);
    cudaGetSymbolAddress((void**)&p_wig, g_wig);
    cudaGetSymbolAddress((void**)&p_wog, g_wog);
    cudaGetSymbolAddress((void**)&p_wo,  g_wo);

    // 0) RN tf32 conversions for GEMM operands
    conv_tf32_kernel<<<(NTOK*HH/4 + 255)/256, 256>>>(x,   p_xt,  NTOK*HH/4);
    conv_tf32_kernel<<<(HH*HH/4 + 255)/256,   256>>>(Wig, p_wig, HH*HH/4);
    conv_tf32_kernel<<<(HH*HH/4 + 255)/256,   256>>>(Wog, p_wog, HH*HH/4);
    conv_tf32_kernel<<<(HH*HH/4 + 255)/256,   256>>>(Wo,  p_wo,  HH*HH/4);

    // 1) projections + gating precompute + intra-chunk A
    qk_chunk_kernel<<<BB*NCC, 256, SMEM1_BYTES>>>(x, Wq, Wk);
    // 2) chunked recurrence -> g_o (tf32-rounded)
    recurrence_kernel<<<dim3(HH/32, BB), 256, SMEM2_BYTES>>>(x);
    // 3) go = x @ Wig^T + o @ Wog^T  (one dual-source tf32 GEMM, K=4096)
    gemm_mma_kernel<<<dim3(HH/128, NTOK/128), 256>>>(p_xt, p_wig, p_o, p_wog, p_go, 256);
    // 4) h = rmsnorm(o)*g * silu(go)  (in place, tf32-rounded)
    rms_silu_kernel<<<NTOK, 256>>>(gnw);
    // 5) out = h @ Wo^T
    gemm_mma_kernel<<<dim3(HH/128, NTOK/128), 256>>>(p_o, p_wo, p_o, p_wo, out, 128);
}

// round 7
// speedup vs baseline: 1.9391x; 1.0853x over previous
#include <cuda_runtime.h>
#include <math.h>
#include <stdint.h>

#define BB   2
#define LL   4096
#define HH   2048
#define DKK  128
#define CCH  64          // chunk length C
#define NCC  64          // chunks per batch
#define NTOK (BB*LL)     // 8192 tokens

// ---------------- scratch (static device globals; no allocation) ----------------
__device__ __align__(16) float g_qe[BB*LL*DKK];                 // q * exp(B)
__device__ __align__(16) float g_kd[BB*LL*DKK];                 // k * exp(Blast - B)
__device__ __align__(16) float g_eL[BB*NCC*DKK];                // exp(Blast)
__device__ __align__(16) float g_A [BB*NCC*CCH*CCH];            // intra-chunk A (tril)
__device__ __align__(16) float g_o [(size_t)NTOK*HH];           // GLA output (tf32-rounded), later h
__device__ __align__(16) float g_go[(size_t)NTOK*HH];           // gate pre-activation
__device__ __align__(16) float g_qk[(size_t)NTOK*256];          // q/k logits (ldc=256)
__device__ __align__(16) float g_xt [(size_t)NTOK*HH];          // tf32-rounded x
__device__ __align__(16) float g_wq [(size_t)DKK*HH];           // tf32-rounded Wq
__device__ __align__(16) float g_wk [(size_t)DKK*HH];           // tf32-rounded Wk
__device__ __align__(16) float g_wig[(size_t)HH*HH];            // tf32-rounded Wig
__device__ __align__(16) float g_wog[(size_t)HH*HH];            // tf32-rounded Wog
__device__ __align__(16) float g_wo [(size_t)HH*HH];            // tf32-rounded Wo

// ================================ helpers ========================================
__device__ __forceinline__ float tf32r(float x) {
    uint32_t o;
    asm("cvt.rna.tf32.f32 %0, %1;" : "=r"(o) : "f"(x));
    return __uint_as_float(o);
}

// D += A*B : m16n8k8 tf32 (sm_80+ PTX, runs on plain sm_103)
__device__ __forceinline__ void mma16n8k8(float d[4],
                                          uint32_t a0, uint32_t a1, uint32_t a2, uint32_t a3,
                                          uint32_t b0, uint32_t b1) {
    asm("mma.sync.aligned.m16n8k8.row.col.f32.tf32.tf32.f32 "
        "{%0,%1,%2,%3}, {%4,%5,%6,%7}, {%8,%9}, {%0,%1,%2,%3};"
        : "+f"(d[0]), "+f"(d[1]), "+f"(d[2]), "+f"(d[3])
        : "r"(a0), "r"(a1), "r"(a2), "r"(a3), "r"(b0), "r"(b1));
}

// =================================================================================
// Kernel 0: RN round to tf32
// =================================================================================
__global__ void __launch_bounds__(256) conv_tf32_kernel(
    const float* __restrict__ src, float* __restrict__ dst, int n4)
{
    int i = blockIdx.x*256 + threadIdx.x;
    if (i < n4) {
        float4 v = ((const float4*)src)[i];
        v.x = tf32r(v.x); v.y = tf32r(v.y); v.z = tf32r(v.z); v.w = tf32r(v.w);
        ((float4*)dst)[i] = v;
    }
}

// =================================================================================
// tf32 mma.sync GEMM.  C[M,*] = A@B^T.  CTA tile 128x128, BK=16, 8 warps (2x4),
// each 64x32 warp tile of m16n8k8. smem k-major [k][m] pad 132.
// DUALN=0: dual-K source (switch A/B at ktile 128), C col base = blockIdx.x*128.
// DUALN=1: B selected by blockIdx.x (B1/B2), C col base = blockIdx.x*128, n0=0.
// =================================================================================
#define PADM 132

template<int DUALN>
__global__ void __launch_bounds__(256) gemm_mma_kernel(
    const float* __restrict__ A1, const float* __restrict__ B1,
    const float* __restrict__ A2, const float* __restrict__ B2,
    float* __restrict__ Cmat, int nk, int ldc)
{
    __shared__ float As[2][16*PADM];
    __shared__ float Bs[2][16*PADM];

    const int tid = threadIdx.x;
    const int m0 = blockIdx.y * 128;
    int n0, co;
    const float* Bsel = B1;
    if (DUALN) {
        n0 = 0; co = blockIdx.x * 128;
        if (blockIdx.x) Bsel = B2;
    } else {
        n0 = blockIdx.x * 128; co = n0;
    }
    const int row = tid >> 2;            // 0..63 (loader row)
    const int kk4 = (tid & 3) << 2;      // 0,4,8,12
    const int warp = tid >> 5, lane = tid & 31;
    const int wm = (warp & 1) * 64;      // warp m offset
    const int wn = (warp >> 1) * 32;     // warp n offset
    const int g = lane >> 2, t = lane & 3;

    float acc[4][4][4];
#pragma unroll
    for (int i = 0; i < 4; i++)
#pragma unroll
        for (int j = 0; j < 4; j++)
#pragma unroll
            for (int k = 0; k < 4; k++) acc[i][j][k] = 0.f;

    float4 ra0, ra1, rb0, rb1;

    // ---- load ktile 0 ----
    {
        const float* Ab = A1 + (size_t)(m0 + row) * HH + kk4;
        const float* Bb = Bsel + (size_t)(n0 + row) * HH + kk4;
        ra0 = *(const float4*)(Ab);
        ra1 = *(const float4*)(Ab + (size_t)64 * HH);
        rb0 = *(const float4*)(Bb);
        rb1 = *(const float4*)(Bb + (size_t)64 * HH);
    }
#pragma unroll
    for (int j = 0; j < 4; j++) {
        As[0][(kk4+j)*PADM + row]      = ((float*)&ra0)[j];
        As[0][(kk4+j)*PADM + row + 64] = ((float*)&ra1)[j];
        Bs[0][(kk4+j)*PADM + row]      = ((float*)&rb0)[j];
        Bs[0][(kk4+j)*PADM + row + 64] = ((float*)&rb1)[j];
    }
    __syncthreads();

    for (int kt = 0; kt < nk; kt++) {
        const int cur = kt & 1;
        if (kt + 1 < nk) {
            int nx = kt + 1;
            const float* Ab; const float* Bb;
            if (DUALN) { Ab = A1; Bb = Bsel; }
            else if (nx < 128) { Ab = A1; Bb = B1; }
            else { Ab = A2; Bb = B2; }
            int kof = (nx & 127) * 16 + kk4;
            Ab += (size_t)(m0 + row) * HH + kof;
            Bb += (size_t)(n0 + row) * HH + kof;
            ra0 = *(const float4*)(Ab);
            ra1 = *(const float4*)(Ab + (size_t)64 * HH);
            rb0 = *(const float4*)(Bb);
            rb1 = *(const float4*)(Bb + (size_t)64 * HH);
        }

#pragma unroll
        for (int ks = 0; ks < 2; ks++) {
            const float* pAlo = &As[cur][(ks*8 + t)*PADM];
            const float* pAhi = &As[cur][(ks*8 + t + 4)*PADM];
            const float* pBlo = &Bs[cur][(ks*8 + t)*PADM];
            const float* pBhi = &Bs[cur][(ks*8 + t + 4)*PADM];

            uint32_t a[4][4];
#pragma unroll
            for (int mt = 0; mt < 4; mt++) {
                int r = wm + mt*16 + g;
                a[mt][0] = __float_as_uint(pAlo[r]);
                a[mt][1] = __float_as_uint(pAlo[r + 8]);
                a[mt][2] = __float_as_uint(pAhi[r]);
                a[mt][3] = __float_as_uint(pAhi[r + 8]);
            }
            uint32_t b[4][2];
#pragma unroll
            for (int nt = 0; nt < 4; nt++) {
                int cidx = wn + nt*8 + g;
                b[nt][0] = __float_as_uint(pBlo[cidx]);
                b[nt][1] = __float_as_uint(pBhi[cidx]);
            }
#pragma unroll
            for (int mt = 0; mt < 4; mt++)
#pragma unroll
                for (int nt = 0; nt < 4; nt++)
                    mma16n8k8(acc[mt][nt],
                              a[mt][0], a[mt][1], a[mt][2], a[mt][3],
                              b[nt][0], b[nt][1]);
        }

        if (kt + 1 < nk) {
            const int nxt = cur ^ 1;
#pragma unroll
            for (int j = 0; j < 4; j++) {
                As[nxt][(kk4+j)*PADM + row]      = ((float*)&ra0)[j];
                As[nxt][(kk4+j)*PADM + row + 64] = ((float*)&ra1)[j];
                Bs[nxt][(kk4+j)*PADM + row]      = ((float*)&rb0)[j];
                Bs[nxt][(kk4+j)*PADM + row + 64] = ((float*)&rb1)[j];
            }
        }
        __syncthreads();
    }

    // ---- epilogue ----
#pragma unroll
    for (int mt = 0; mt < 4; mt++) {
        int r0 = m0 + wm + mt*16 + g;
#pragma unroll
        for (int nt = 0; nt < 4; nt++) {
            int c = co + wn + nt*8 + 2*t;
            *(float2*)(Cmat + (size_t)r0*ldc + c) =
                make_float2(acc[mt][nt][0], acc[mt][nt][1]);
            *(float2*)(Cmat + (size_t)(r0+8)*ldc + c) =
                make_float2(acc[mt][nt][2], acc[mt][nt][3]);
        }
    }
}

// =================================================================================
// Kernel 1 (new): gate_kernel — per chunk: softmax(q) / sigmoid(k) / cumsum B,
// qe/kd/eL outputs, and A = (q e^{B-Bmid}) @ (k e^{Bmid-B})^T with tril mask.
// grid = 128 blocks, 256 threads.
// =================================================================================
#define PADG 129
#define GATE_FLOATS (3*64*PADG + 3*128)
#define GATE_BYTES  (GATE_FLOATS*4)

__global__ void __launch_bounds__(256) gate_kernel()
{
    extern __shared__ float sm[];
    float* ql   = sm;                 // 64*PADG : q logits -> softmax -> qe2
    float* kl   = sm + 64*PADG;       // 64*PADG : k sigmoid -> ke2
    float* bs   = sm + 2*64*PADG;     // 64*PADG : cumsum B
    float* bmid = sm + 3*64*PADG;     // 128 : B at mid token
    float* eBm  = bmid + 128;         // 128 : exp(Bmid)
    float* eBlm = bmid + 256;         // 128 : exp(Blast - Bmid)

    const int blk = blockIdx.x;
    const int b = blk / NCC, c = blk % NCC;
    const int tid = threadIdx.x;
    const int r0 = b*LL + c*CCH;

    // load logits; apply sigmoid to k
    for (int idx = tid; idx < 64*128; idx += 256) {
        int t = idx >> 7, d = idx & 127;
        const float* gr = g_qk + (size_t)(r0 + t) * 256;
        ql[t*PADG + d] = gr[d];
        kl[t*PADG + d] = 1.f / (1.f + __expf(-gr[128 + d]));
    }
    __syncthreads();

    // warps 0-1: softmax q rows;  warps 4-7: per-channel cumsum (parallel)
    if (tid < 64) {
        float* r = ql + tid*PADG;
        float m = -1e30f;
        for (int d = 0; d < 128; d++) m = fmaxf(m, r[d]);
        float s = 0.f;
        for (int d = 0; d < 128; d++) { float e = __expf(r[d] - m); r[d] = e; s += e; }
        float inv = 1.f / s;
        for (int d = 0; d < 128; d++) r[d] *= inv;
    }
    if (tid >= 128) {
        int d = tid - 128;
        float acc = 0.f;
        for (int t = 0; t < 64; t++) {
            acc += -log1pf(__expf(kl[t*PADG + d]));
            bs[t*PADG + d] = acc;
        }
        float Bm = bs[31*PADG + d];
        bmid[d] = Bm;
        eBm[d]  = __expf(Bm);
        eBlm[d] = __expf(acc - Bm);
        g_eL[blk*128 + d] = __expf(acc);
    }
    __syncthreads();

    // qe2/ke2 (in place) + qe/kd to gmem
    size_t gbase = (size_t)r0 * DKK;
    for (int idx = tid; idx < 64*128; idx += 256) {
        int t = idx >> 7, d = idx & 127;
        float bv = bs[t*PADG + d] - bmid[d];
        float e1 = __expf(bv);     // e^{B-Bmid}  (<= 1 for t>31, <= e^42 for t<32)
        float e2 = __expf(-bv);
        float q2 = ql[t*PADG + d] * e1;
        float k2 = kl[t*PADG + d] * e2;
        ql[t*PADG + d] = q2;
        kl[t*PADG + d] = k2;
        g_qe[gbase + idx] = q2 * eBm[d];
        g_kd[gbase + idx] = k2 * eBlm[d];
    }
    __syncthreads();

    // A = qe2 @ ke2^T (tril), 16x16 thread grid, 4x4 micro-tile
    const int tr = (tid >> 4) * 4;
    const int tc = (tid & 15) * 4;
    float a4[4][4];
#pragma unroll
    for (int r = 0; r < 4; r++)
#pragma unroll
        for (int cc = 0; cc < 4; cc++) a4[r][cc] = 0.f;
    for (int d = 0; d < 128; d++) {
        float qv[4], kv[4];
#pragma unroll
        for (int r = 0; r < 4; r++)  qv[r]  = ql[(tr+r)*PADG + d];
#pragma unroll
        for (int cc = 0; cc < 4; cc++) kv[cc] = kl[(tc+cc)*PADG + d];
#pragma unroll
        for (int r = 0; r < 4; r++)
#pragma unroll
            for (int cc = 0; cc < 4; cc++) a4[r][cc] += qv[r]*kv[cc];
    }
    float* Ag = g_A + (size_t)blk * CCH * CCH;
#pragma unroll
    for (int r = 0; r < 4; r++)
#pragma unroll
        for (int cc = 0; cc < 4; cc++)
            Ag[(tr+r)*64 + tc+cc] = (tr+r >= tc+cc) ? a4[r][cc] : 0.f;
}

// =================================================================================
// Kernel 2: chunked GLA recurrence (o stores are tf32-rounded for the tf32 GEMM)
// =================================================================================
#define SMEM2_FLOATS (8192 + 8192 + 4096 + 2048 + 4096 + 128)
#define SMEM2_BYTES  (SMEM2_FLOATS*4)

__global__ void __launch_bounds__(256) recurrence_kernel(const float* __restrict__ x)
{
    extern __shared__ float sm[];
    float* qe_s = sm;              // 64*128
    float* kd_s = sm + 8192;       // 64*128
    float* A_s  = sm + 16384;      // 64*64
    float* v_s  = sm + 20480;      // 64*32
    float* S_s  = sm + 22528;      // 128*32
    float* eL_s = sm + 26624;      // 128

    const int b  = blockIdx.y;
    const int v0 = blockIdx.x * 32;
    const int tid = threadIdx.x;
    const int tx = tid & 15;
    const int ty = tid >> 4;
    const int vv = 2*tx;

    for (int i = tid; i < 128*32; i += 256) S_s[i] = 0.f;

    for (int c = 0; c < NCC; c++) {
        __syncthreads();
        {
            size_t base = ((size_t)(b*LL + c*CCH)) * DKK;
            for (int idx = tid*4; idx < 8192; idx += 1024) {
                *(float4*)(qe_s + idx) = *(const float4*)(g_qe + base + idx);
                *(float4*)(kd_s + idx) = *(const float4*)(g_kd + base + idx);
            }
            const float* Ag = g_A + (size_t)(b*NCC + c) * 4096;
            for (int idx = tid*4; idx < 4096; idx += 1024)
                *(float4*)(A_s + idx) = *(const float4*)(Ag + idx);
            for (int idx = tid; idx < 64*32; idx += 256) {
                int t = idx >> 5, j = idx & 31;
                v_s[idx] = x[((size_t)(b*LL + c*CCH + t)) * HH + v0 + j];
            }
            if (tid < 128) eL_s[tid] = g_eL[(b*NCC + c)*128 + tid];
        }
        __syncthreads();

        float o0[4] = {0,0,0,0}, o1[4] = {0,0,0,0};
        for (int j = 0; j < 64; j++) {
            float2 vj = *(float2*)(v_s + j*32 + vv);
#pragma unroll
            for (int r = 0; r < 4; r++) {
                float a = A_s[(ty + 16*r)*64 + j];
                o0[r] += a * vj.x; o1[r] += a * vj.y;
            }
        }
        for (int d = 0; d < 128; d++) {
            float2 sv = *(float2*)(S_s + d*32 + vv);
#pragma unroll
            for (int r = 0; r < 4; r++) {
                float qv = qe_s[(ty + 16*r)*128 + d];
                o0[r] += qv * sv.x; o1[r] += qv * sv.y;
            }
        }
#pragma unroll
        for (int r = 0; r < 4; r++) {
            size_t row = (size_t)(b*LL + c*CCH + ty + 16*r);
            *(float2*)(g_o + row*HH + v0 + vv) = make_float2(tf32r(o0[r]), tf32r(o1[r]));
        }

        float a0[8] = {0,0,0,0,0,0,0,0}, a1[8] = {0,0,0,0,0,0,0,0};
        for (int j = 0; j < 64; j++) {
            float2 vj = *(float2*)(v_s + j*32 + vv);
            float4 k0 = *(float4*)(kd_s + j*128 + ty*8);
            float4 k1 = *(float4*)(kd_s + j*128 + ty*8 + 4);
            a0[0] += k0.x*vj.x; a1[0] += k0.x*vj.y;
            a0[1] += k0.y*vj.x; a1[1] += k0.y*vj.y;
            a0[2] += k0.z*vj.x; a1[2] += k0.z*vj.y;
            a0[3] += k0.w*vj.x; a1[3] += k0.w*vj.y;
            a0[4] += k1.x*vj.x; a1[4] += k1.x*vj.y;
            a0[5] += k1.y*vj.x; a1[5] += k1.y*vj.y;
            a0[6] += k1.z*vj.x; a1[6] += k1.z*vj.y;
            a0[7] += k1.w*vj.x; a1[7] += k1.w*vj.y;
        }
        __syncthreads();
#pragma unroll
        for (int dd = 0; dd < 8; dd++) {
            int d = ty*8 + dd;
            float e = eL_s[d];
            S_s[d*32 + vv]     = S_s[d*32 + vv]     * e + a0[dd];
            S_s[d*32 + vv + 1] = S_s[d*32 + vv + 1] * e + a1[dd];
        }
    }
}

// =================================================================================
// Kernel 4: h = rmsnorm(o)*g * silu(go)  (in-place into g_o, tf32-rounded)
// =================================================================================
__global__ void __launch_bounds__(256) rms_silu_kernel(const float* __restrict__ gnw)
{
    __shared__ float red[256];
    const size_t row = blockIdx.x;
    float* orow  = g_o  + row * HH;
    const float* gorow = g_go + row * HH;
    const int tid = threadIdx.x;

    float s = 0.f;
    for (int i = tid; i < HH; i += 256) { float v = orow[i]; s += v*v; }
    red[tid] = s;
    __syncthreads();
    for (int off = 128; off > 0; off >>= 1) {
        if (tid < off) red[tid] += red[tid + off];
        __syncthreads();
    }
    float rinv = rsqrtf(red[0] * (1.f / (float)HH) + 1e-5f);

    for (int i = tid; i < HH; i += 256) {
        float ov = orow[i] * rinv * gnw[i];
        float g  = gorow[i];
        float sig = 1.f / (1.f + __expf(-g));
        orow[i] = tf32r(ov * (g * sig));
    }
}

// ================================= host side =====================================
extern "C" void kernel_launch(void* const* d_in, const int* in_sizes, int n_in,
                              void* d_out, int out_size)
{
    const float* x   = (const float*)d_in[0];
    const float* Wq  = (const float*)d_in[1];
    const float* Wk  = (const float*)d_in[2];
    const float* Wog = (const float*)d_in[3];
    const float* Wig = (const float*)d_in[4];
    const float* Wo  = (const float*)d_in[5];
    const float* gnw = (const float*)d_in[6];
    float* out = (float*)d_out;

    cudaFuncSetAttribute(gate_kernel,
                         cudaFuncAttributeMaxDynamicSharedMemorySize, GATE_BYTES);
    cudaFuncSetAttribute(recurrence_kernel,
                         cudaFuncAttributeMaxDynamicSharedMemorySize, SMEM2_BYTES);

    float *p_o, *p_go, *p_qk, *p_xt, *p_wq, *p_wk, *p_wig, *p_wog, *p_wo;
    cudaGetSymbolAddress((void**)&p_o,   g_o);
    cudaGetSymbolAddress((void**)&p_go,  g_go);
    cudaGetSymbolAddress((void**)&p_qk,  g_qk);
    cudaGetSymbolAddress((void**)&p_xt,  g_xt);
    cudaGetSymbolAddress((void**)&p_wq,  g_wq);
    cudaGetSymbolAddress((void**)&p_wk,  g_wk);
    cudaGetSymbolAddress((void**)&p_wig, g_wig);
    cudaGetSymbolAddress((void**)&p_wog, g_wog);
    cudaGetSymbolAddress((void**)&p_wo,  g_wo);

    // 0) RN tf32 conversions for all GEMM operands
    conv_tf32_kernel<<<(NTOK*HH/4 + 255)/256, 256>>>(x,   p_xt,  NTOK*HH/4);
    conv_tf32_kernel<<<(DKK*HH/4 + 255)/256,  256>>>(Wq,  p_wq,  DKK*HH/4);
    conv_tf32_kernel<<<(DKK*HH/4 + 255)/256,  256>>>(Wk,  p_wk,  DKK*HH/4);
    conv_tf32_kernel<<<(HH*HH/4 + 255)/256,   256>>>(Wig, p_wig, HH*HH/4);
    conv_tf32_kernel<<<(HH*HH/4 + 255)/256,   256>>>(Wog, p_wog, HH*HH/4);
    conv_tf32_kernel<<<(HH*HH/4 + 255)/256,   256>>>(Wo,  p_wo,  HH*HH/4);

    // 1) q/k logits: ql = x@Wq^T, kl = x@Wk^T  (one dual-N tensor GEMM)
    gemm_mma_kernel<1><<<dim3(2, NTOK/128), 256>>>(p_xt, p_wq, p_xt, p_wk, p_qk, 128, 256);
    // 2) gating precompute + intra-chunk A (separable, exp-free inner loop)
    gate_kernel<<<BB*NCC, 256, GATE_BYTES>>>();
    // 3) chunked recurrence -> g_o (tf32-rounded)
    recurrence_kernel<<<dim3(HH/32, BB), 256, SMEM2_BYTES>>>(x);
    // 4) go = x @ Wig^T + o @ Wog^T  (one dual-K tensor GEMM, K=4096)
    gemm_mma_kernel<0><<<dim3(HH/128, NTOK/128), 256>>>(p_xt, p_wig, p_o, p_wog, p_go, 256, HH);
    // 5) h = rmsnorm(o)*g * silu(go)  (in place, tf32-rounded)
    rms_silu_kernel<<<NTOK, 256>>>(gnw);
    // 6) out = h @ Wo^T
    gemm_mma_kernel<0><<<dim3(HH/128, NTOK/128), 256>>>(p_o, p_wo, p_o, p_wo, out, 128, HH);
}

// round 8
// speedup vs baseline: 2.0052x; 1.0341x over previous
#include <cuda_runtime.h>
#include <math.h>
#include <stdint.h>

#define BB   2
#define LL   4096
#define HH   2048
#define DKK  128
#define CCH  64          // chunk length C
#define NCC  64          // chunks per batch
#define NTOK (BB*LL)     // 8192 tokens

// ---------------- scratch (static device globals; no allocation) ----------------
__device__ __align__(16) float g_qe[BB*LL*DKK];                 // q * exp(B)
__device__ __align__(16) float g_kd[BB*LL*DKK];                 // k * exp(Blast - B)
__device__ __align__(16) float g_eL[BB*NCC*DKK];                // exp(Blast)
__device__ __align__(16) float g_A [BB*NCC*CCH*CCH];            // intra-chunk A (tril)
__device__ __align__(16) float g_o [(size_t)NTOK*HH];           // GLA output, later h
__device__ __align__(16) float g_go[(size_t)NTOK*HH];           // gate pre-activation
__device__ __align__(16) float g_qk[(size_t)NTOK*256];          // q/k logits (ldc=256)

// ================================ helpers ========================================
__device__ __forceinline__ float tf32r(float x) {
    uint32_t o;
    asm("cvt.rna.tf32.f32 %0, %1;" : "=r"(o) : "f"(x));
    return __uint_as_float(o);
}
__device__ __forceinline__ float4 ld4tf(const float* p) {
    float4 v = *(const float4*)p;
    v.x = tf32r(v.x); v.y = tf32r(v.y); v.z = tf32r(v.z); v.w = tf32r(v.w);
    return v;
}

// D += A*B : m16n8k8 tf32 (sm_80+ PTX, runs on plain sm_103)
__device__ __forceinline__ void mma16n8k8(float d[4],
                                          uint32_t a0, uint32_t a1, uint32_t a2, uint32_t a3,
                                          uint32_t b0, uint32_t b1) {
    asm("mma.sync.aligned.m16n8k8.row.col.f32.tf32.tf32.f32 "
        "{%0,%1,%2,%3}, {%4,%5,%6,%7}, {%8,%9}, {%0,%1,%2,%3};"
        : "+f"(d[0]), "+f"(d[1]), "+f"(d[2]), "+f"(d[3])
        : "r"(a0), "r"(a1), "r"(a2), "r"(a3), "r"(b0), "r"(b1));
}

// =================================================================================
// tf32 mma.sync GEMM.  C[M,*] = A@B^T.  CTA tile 128x128, BK=16, 8 warps (2x4),
// each 64x32 warp tile of m16n8k8.
// smem: m-major, permuted k so fragment pairs (k=t, k=t+4) are adjacent ->
// A frag = 2x LDS.64, B frag = 1x LDS.64. Row stride SK=24 (conflict-free).
// Loader applies cvt.rna.tf32 (inputs are raw fp32).
// DUALN=0: dual-K source (switch A/B at ktile 128), C col base = blockIdx.x*128.
// DUALN=1: B selected by blockIdx.x (B1/B2), C col base = blockIdx.x*128, n0=0.
// =================================================================================
#define SK 24

template<int DUALN>
__global__ void __launch_bounds__(256) gemm_mma_kernel(
    const float* __restrict__ A1, const float* __restrict__ B1,
    const float* __restrict__ A2, const float* __restrict__ B2,
    float* __restrict__ Cmat, int nk, int ldc)
{
    __shared__ float As[2][128*SK];
    __shared__ float Bs[2][128*SK];

    const int tid = threadIdx.x;
    const int m0 = blockIdx.y * 128;
    int n0, co;
    const float* Bsel = B1;
    if (DUALN) {
        n0 = 0; co = blockIdx.x * 128;
        if (blockIdx.x) Bsel = B2;
    } else {
        n0 = blockIdx.x * 128; co = n0;
    }
    const int row = tid >> 2;            // 0..63 (loader row)
    const int kk4 = (tid & 3) << 2;      // 0,4,8,12
    // permuted k position base: perm(kk4+j) = pbase + 2*j
    const int pbase = ((kk4 >> 2) & 1) + (kk4 & 8);
    const int warp = tid >> 5, lane = tid & 31;
    const int wm = (warp & 1) * 64;      // warp m offset
    const int wn = (warp >> 1) * 32;     // warp n offset
    const int g = lane >> 2, t = lane & 3;

    float acc[4][4][4];
#pragma unroll
    for (int i = 0; i < 4; i++)
#pragma unroll
        for (int j = 0; j < 4; j++)
#pragma unroll
            for (int k = 0; k < 4; k++) acc[i][j][k] = 0.f;

    float4 ra0, ra1, rb0, rb1;

    // ---- load ktile 0 ----
    {
        const float* Ab = A1 + (size_t)(m0 + row) * HH + kk4;
        const float* Bb = Bsel + (size_t)(n0 + row) * HH + kk4;
        ra0 = ld4tf(Ab);
        ra1 = ld4tf(Ab + (size_t)64 * HH);
        rb0 = ld4tf(Bb);
        rb1 = ld4tf(Bb + (size_t)64 * HH);
    }
#pragma unroll
    for (int j = 0; j < 4; j++) {
        As[0][(row)*SK    + pbase + 2*j] = ((float*)&ra0)[j];
        As[0][(row+64)*SK + pbase + 2*j] = ((float*)&ra1)[j];
        Bs[0][(row)*SK    + pbase + 2*j] = ((float*)&rb0)[j];
        Bs[0][(row+64)*SK + pbase + 2*j] = ((float*)&rb1)[j];
    }
    __syncthreads();

    for (int kt = 0; kt < nk; kt++) {
        const int cur = kt & 1;
        if (kt + 1 < nk) {
            int nx = kt + 1;
            const float* Ab; const float* Bb;
            if (DUALN) { Ab = A1; Bb = Bsel; }
            else if (nx < 128) { Ab = A1; Bb = B1; }
            else { Ab = A2; Bb = B2; }
            int kof = (nx & 127) * 16 + kk4;
            Ab += (size_t)(m0 + row) * HH + kof;
            Bb += (size_t)(n0 + row) * HH + kof;
            ra0 = ld4tf(Ab);
            ra1 = ld4tf(Ab + (size_t)64 * HH);
            rb0 = ld4tf(Bb);
            rb1 = ld4tf(Bb + (size_t)64 * HH);
        }

#pragma unroll
        for (int ks = 0; ks < 2; ks++) {
            const int kb = ks*8 + 2*t;
            uint32_t a[4][4];
#pragma unroll
            for (int mt = 0; mt < 4; mt++) {
                int r = wm + mt*16 + g;
                float2 lo = *(const float2*)&As[cur][r*SK + kb];
                float2 hi = *(const float2*)&As[cur][(r+8)*SK + kb];
                a[mt][0] = __float_as_uint(lo.x);
                a[mt][1] = __float_as_uint(hi.x);
                a[mt][2] = __float_as_uint(lo.y);
                a[mt][3] = __float_as_uint(hi.y);
            }
            uint32_t b[4][2];
#pragma unroll
            for (int nt = 0; nt < 4; nt++) {
                int c = wn + nt*8 + g;
                float2 bb = *(const float2*)&Bs[cur][c*SK + kb];
                b[nt][0] = __float_as_uint(bb.x);
                b[nt][1] = __float_as_uint(bb.y);
            }
#pragma unroll
            for (int mt = 0; mt < 4; mt++)
#pragma unroll
                for (int nt = 0; nt < 4; nt++)
                    mma16n8k8(acc[mt][nt],
                              a[mt][0], a[mt][1], a[mt][2], a[mt][3],
                              b[nt][0], b[nt][1]);
        }

        if (kt + 1 < nk) {
            const int nxt = cur ^ 1;
#pragma unroll
            for (int j = 0; j < 4; j++) {
                As[nxt][(row)*SK    + pbase + 2*j] = ((float*)&ra0)[j];
                As[nxt][(row+64)*SK + pbase + 2*j] = ((float*)&ra1)[j];
                Bs[nxt][(row)*SK    + pbase + 2*j] = ((float*)&rb0)[j];
                Bs[nxt][(row+64)*SK + pbase + 2*j] = ((float*)&rb1)[j];
            }
        }
        __syncthreads();
    }

    // ---- epilogue ----
#pragma unroll
    for (int mt = 0; mt < 4; mt++) {
        int r0 = m0 + wm + mt*16 + g;
#pragma unroll
        for (int nt = 0; nt < 4; nt++) {
            int c = co + wn + nt*8 + 2*t;
            *(float2*)(Cmat + (size_t)r0*ldc + c) =
                make_float2(acc[mt][nt][0], acc[mt][nt][1]);
            *(float2*)(Cmat + (size_t)(r0+8)*ldc + c) =
                make_float2(acc[mt][nt][2], acc[mt][nt][3]);
        }
    }
}

// =================================================================================
// gate_kernel — per chunk: softmax(q) / sigmoid(k) / cumsum B, qe/kd/eL outputs,
// and A = (q e^{B-Bmid}) @ (k e^{Bmid-B})^T with tril mask.  grid = 128 blocks.
// =================================================================================
#define PADG 129
#define GATE_FLOATS (3*64*PADG + 3*128)
#define GATE_BYTES  (GATE_FLOATS*4)

__global__ void __launch_bounds__(256) gate_kernel()
{
    extern __shared__ float sm[];
    float* ql   = sm;                 // 64*PADG : q logits -> softmax -> qe2
    float* kl   = sm + 64*PADG;       // 64*PADG : k sigmoid -> ke2
    float* bs   = sm + 2*64*PADG;     // 64*PADG : cumsum B
    float* bmid = sm + 3*64*PADG;     // 128 : B at mid token
    float* eBm  = bmid + 128;         // 128 : exp(Bmid)
    float* eBlm = bmid + 256;         // 128 : exp(Blast - Bmid)

    const int blk = blockIdx.x;
    const int b = blk / NCC, c = blk % NCC;
    const int tid = threadIdx.x;
    const int r0 = b*LL + c*CCH;

    for (int idx = tid; idx < 64*128; idx += 256) {
        int t = idx >> 7, d = idx & 127;
        const float* gr = g_qk + (size_t)(r0 + t) * 256;
        ql[t*PADG + d] = gr[d];
        kl[t*PADG + d] = 1.f / (1.f + __expf(-gr[128 + d]));
    }
    __syncthreads();

    if (tid < 64) {
        float* r = ql + tid*PADG;
        float m = -1e30f;
        for (int d = 0; d < 128; d++) m = fmaxf(m, r[d]);
        float s = 0.f;
        for (int d = 0; d < 128; d++) { float e = __expf(r[d] - m); r[d] = e; s += e; }
        float inv = 1.f / s;
        for (int d = 0; d < 128; d++) r[d] *= inv;
    }
    if (tid >= 128) {
        int d = tid - 128;
        float acc = 0.f;
        for (int t = 0; t < 64; t++) {
            acc += -log1pf(__expf(kl[t*PADG + d]));
            bs[t*PADG + d] = acc;
        }
        float Bm = bs[31*PADG + d];
        bmid[d] = Bm;
        eBm[d]  = __expf(Bm);
        eBlm[d] = __expf(acc - Bm);
        g_eL[blk*128 + d] = __expf(acc);
    }
    __syncthreads();

    size_t gbase = (size_t)r0 * DKK;
    for (int idx = tid; idx < 64*128; idx += 256) {
        int t = idx >> 7, d = idx & 127;
        float bv = bs[t*PADG + d] - bmid[d];
        float e1 = __expf(bv);
        float e2 = __expf(-bv);
        float q2 = ql[t*PADG + d] * e1;
        float k2 = kl[t*PADG + d] * e2;
        ql[t*PADG + d] = q2;
        kl[t*PADG + d] = k2;
        g_qe[gbase + idx] = q2 * eBm[d];
        g_kd[gbase + idx] = k2 * eBlm[d];
    }
    __syncthreads();

    const int tr = (tid >> 4) * 4;
    const int tc = (tid & 15) * 4;
    float a4[4][4];
#pragma unroll
    for (int r = 0; r < 4; r++)
#pragma unroll
        for (int cc = 0; cc < 4; cc++) a4[r][cc] = 0.f;
    for (int d = 0; d < 128; d++) {
        float qv[4], kv[4];
#pragma unroll
        for (int r = 0; r < 4; r++)  qv[r]  = ql[(tr+r)*PADG + d];
#pragma unroll
        for (int cc = 0; cc < 4; cc++) kv[cc] = kl[(tc+cc)*PADG + d];
#pragma unroll
        for (int r = 0; r < 4; r++)
#pragma unroll
            for (int cc = 0; cc < 4; cc++) a4[r][cc] += qv[r]*kv[cc];
    }
    float* Ag = g_A + (size_t)blk * CCH * CCH;
#pragma unroll
    for (int r = 0; r < 4; r++)
#pragma unroll
        for (int cc = 0; cc < 4; cc++)
            Ag[(tr+r)*64 + tc+cc] = (tr+r >= tc+cc) ? a4[r][cc] : 0.f;
}

// =================================================================================
// Kernel 2: chunked GLA recurrence. grid (H/32, B), 256 threads.
// =================================================================================
#define SMEM2_FLOATS (8192 + 8192 + 4096 + 2048 + 4096 + 128)
#define SMEM2_BYTES  (SMEM2_FLOATS*4)

__global__ void __launch_bounds__(256) recurrence_kernel(const float* __restrict__ x)
{
    extern __shared__ float sm[];
    float* qe_s = sm;              // 64*128
    float* kd_s = sm + 8192;       // 64*128
    float* A_s  = sm + 16384;      // 64*64
    float* v_s  = sm + 20480;      // 64*32
    float* S_s  = sm + 22528;      // 128*32
    float* eL_s = sm + 26624;      // 128

    const int b  = blockIdx.y;
    const int v0 = blockIdx.x * 32;
    const int tid = threadIdx.x;
    const int tx = tid & 15;
    const int ty = tid >> 4;
    const int vv = 2*tx;

    for (int i = tid; i < 128*32; i += 256) S_s[i] = 0.f;

    for (int c = 0; c < NCC; c++) {
        __syncthreads();
        {
            size_t base = ((size_t)(b*LL + c*CCH)) * DKK;
            for (int idx = tid*4; idx < 8192; idx += 1024) {
                *(float4*)(qe_s + idx) = *(const float4*)(g_qe + base + idx);
                *(float4*)(kd_s + idx) = *(const float4*)(g_kd + base + idx);
            }
            const float* Ag = g_A + (size_t)(b*NCC + c) * 4096;
            for (int idx = tid*4; idx < 4096; idx += 1024)
                *(float4*)(A_s + idx) = *(const float4*)(Ag + idx);
            for (int idx = tid; idx < 64*32; idx += 256) {
                int t = idx >> 5, j = idx & 31;
                v_s[idx] = x[((size_t)(b*LL + c*CCH + t)) * HH + v0 + j];
            }
            if (tid < 128) eL_s[tid] = g_eL[(b*NCC + c)*128 + tid];
        }
        __syncthreads();

        // ---- o = A@v + (q e^B)@S  (rows ty+16r, cols vv,vv+1) ----
        float o0[4] = {0,0,0,0}, o1[4] = {0,0,0,0};
#pragma unroll 4
        for (int j = 0; j < 64; j += 4) {
            float2 vj0 = *(float2*)(v_s + (j+0)*32 + vv);
            float2 vj1 = *(float2*)(v_s + (j+1)*32 + vv);
            float2 vj2 = *(float2*)(v_s + (j+2)*32 + vv);
            float2 vj3 = *(float2*)(v_s + (j+3)*32 + vv);
#pragma unroll
            for (int r = 0; r < 4; r++) {
                float4 a = *(float4*)(A_s + (ty + 16*r)*64 + j);
                o0[r] += a.x*vj0.x + a.y*vj1.x + a.z*vj2.x + a.w*vj3.x;
                o1[r] += a.x*vj0.y + a.y*vj1.y + a.z*vj2.y + a.w*vj3.y;
            }
        }
#pragma unroll 4
        for (int d = 0; d < 128; d += 4) {
            float2 s0 = *(float2*)(S_s + (d+0)*32 + vv);
            float2 s1 = *(float2*)(S_s + (d+1)*32 + vv);
            float2 s2 = *(float2*)(S_s + (d+2)*32 + vv);
            float2 s3 = *(float2*)(S_s + (d+3)*32 + vv);
#pragma unroll
            for (int r = 0; r < 4; r++) {
                float4 q = *(float4*)(qe_s + (ty + 16*r)*128 + d);
                o0[r] += q.x*s0.x + q.y*s1.x + q.z*s2.x + q.w*s3.x;
                o1[r] += q.x*s0.y + q.y*s1.y + q.z*s2.y + q.w*s3.y;
            }
        }
#pragma unroll
        for (int r = 0; r < 4; r++) {
            size_t row = (size_t)(b*LL + c*CCH + ty + 16*r);
            *(float2*)(g_o + row*HH + v0 + vv) = make_float2(o0[r], o1[r]);
        }

        // ---- S-update accumulators: d = ty*8 + dd ----
        float a0[8] = {0,0,0,0,0,0,0,0}, a1[8] = {0,0,0,0,0,0,0,0};
        for (int j = 0; j < 64; j++) {
            float2 vj = *(float2*)(v_s + j*32 + vv);
            float4 k0 = *(float4*)(kd_s + j*128 + ty*8);
            float4 k1 = *(float4*)(kd_s + j*128 + ty*8 + 4);
            a0[0] += k0.x*vj.x; a1[0] += k0.x*vj.y;
            a0[1] += k0.y*vj.x; a1[1] += k0.y*vj.y;
            a0[2] += k0.z*vj.x; a1[2] += k0.z*vj.y;
            a0[3] += k0.w*vj.x; a1[3] += k0.w*vj.y;
            a0[4] += k1.x*vj.x; a1[4] += k1.x*vj.y;
            a0[5] += k1.y*vj.x; a1[5] += k1.y*vj.y;
            a0[6] += k1.z*vj.x; a1[6] += k1.z*vj.y;
            a0[7] += k1.w*vj.x; a1[7] += k1.w*vj.y;
        }
        __syncthreads();
#pragma unroll
        for (int dd = 0; dd < 8; dd++) {
            int d = ty*8 + dd;
            float e = eL_s[d];
            S_s[d*32 + vv]     = S_s[d*32 + vv]     * e + a0[dd];
            S_s[d*32 + vv + 1] = S_s[d*32 + vv + 1] * e + a1[dd];
        }
    }
}

// =================================================================================
// Kernel 4: h = rmsnorm(o)*g * silu(go)  (in-place into g_o)
// =================================================================================
__global__ void __launch_bounds__(256) rms_silu_kernel(const float* __restrict__ gnw)
{
    __shared__ float red[256];
    const size_t row = blockIdx.x;
    float* orow  = g_o  + row * HH;
    const float* gorow = g_go + row * HH;
    const int tid = threadIdx.x;

    float s = 0.f;
#pragma unroll
    for (int i = tid; i < HH/4; i += 256) {
        float4 v = ((const float4*)orow)[i];
        s += v.x*v.x + v.y*v.y + v.z*v.z + v.w*v.w;
    }
    red[tid] = s;
    __syncthreads();
    for (int off = 128; off > 0; off >>= 1) {
        if (tid < off) red[tid] += red[tid + off];
        __syncthreads();
    }
    float rinv = rsqrtf(red[0] * (1.f / (float)HH) + 1e-5f);

#pragma unroll
    for (int i = tid; i < HH/4; i += 256) {
        float4 ov = ((const float4*)orow)[i];
        float4 gv = ((const float4*)gorow)[i];
        float4 wv = ((const float4*)gnw)[i];
        float4 o4;
        {
            float a = ov.x * rinv * wv.x, g = gv.x;
            o4.x = a * (g / (1.f + __expf(-g)));
        }
        {
            float a = ov.y * rinv * wv.y, g = gv.y;
            o4.y = a * (g / (1.f + __expf(-g)));
        }
        {
            float a = ov.z * rinv * wv.z, g = gv.z;
            o4.z = a * (g / (1.f + __expf(-g)));
        }
        {
            float a = ov.w * rinv * wv.w, g = gv.w;
            o4.w = a * (g / (1.f + __expf(-g)));
        }
        ((float4*)orow)[i] = o4;
    }
}

// ================================= host side =====================================
extern "C" void kernel_launch(void* const* d_in, const int* in_sizes, int n_in,
                              void* d_out, int out_size)
{
    const float* x   = (const float*)d_in[0];
    const float* Wq  = (const float*)d_in[1];
    const float* Wk  = (const float*)d_in[2];
    const float* Wog = (const float*)d_in[3];
    const float* Wig = (const float*)d_in[4];
    const float* Wo  = (const float*)d_in[5];
    const float* gnw = (const float*)d_in[6];
    float* out = (float*)d_out;

    cudaFuncSetAttribute(gate_kernel,
                         cudaFuncAttributeMaxDynamicSharedMemorySize, GATE_BYTES);
    cudaFuncSetAttribute(recurrence_kernel,
                         cudaFuncAttributeMaxDynamicSharedMemorySize, SMEM2_BYTES);

    float *p_o, *p_go, *p_qk;
    cudaGetSymbolAddress((void**)&p_o,  g_o);
    cudaGetSymbolAddress((void**)&p_go, g_go);
    cudaGetSymbolAddress((void**)&p_qk, g_qk);

    // 1) q/k logits: ql = x@Wq^T, kl = x@Wk^T  (one dual-N tensor GEMM; cvt in loader)
    gemm_mma_kernel<1><<<dim3(2, NTOK/128), 256>>>(x, Wq, x, Wk, p_qk, 128, 256);
    // 2) gating precompute + intra-chunk A (separable, exp-free inner loop)
    gate_kernel<<<BB*NCC, 256, GATE_BYTES>>>();
    // 3) chunked recurrence -> g_o
    recurrence_kernel<<<dim3(HH/32, BB), 256, SMEM2_BYTES>>>(x);
    // 4) go = x @ Wig^T + o @ Wog^T  (one dual-K tensor GEMM, K=4096)
    gemm_mma_kernel<0><<<dim3(HH/128, NTOK/128), 256>>>(x, Wig, p_o, Wog, p_go, 256, HH);
    // 5) h = rmsnorm(o)*g * silu(go)  (in place)
    rms_silu_kernel<<<NTOK, 256>>>(gnw);
    // 6) out = h @ Wo^T
    gemm_mma_kernel<0><<<dim3(HH/128, NTOK/128), 256>>>(p_o, Wo, p_o, Wo, out, 128, HH);
}